// round 17
// baseline (speedup 1.0000x reference)
#include <cuda_runtime.h>
#include <cuda_fp16.h>
#include <cstdint>

// GRU decoder, H=4096, T=2048. Persistent single kernel + software grid barrier.
// R2: fp16 weight scratch -> L2-resident.   R6: batched loads + fast gates.
// R9: 9 warps' weights pinned in SMEM -> DRAM ~0%.
// R10: fp16 h in smem.  R12: Stage B on pinned warps.
// R13: flat HFMA2 group-flushed dots + fp16 h global buffer.
// R16: interleaved per-row weight blocks (1 base reg, immediate offsets). [14.80 ms]
// R17: register-carried recurrence. The warp that writes h_new[i] at step t
//      is the one that needs h_old[i] at t+1 -> carry it in a register.
//      Deletes the fp32 g_h array, one LDG + one STG per warp per step, and
//      removes a 234-cyc L2 dependency from each step's critical path.

#define HDIM 4096
#define IN_DIM 400
#define OROWS 401
#define NOUT 400
#define WARPS_PER_BLOCK 28
#define NTHREADS (WARPS_PER_BLOCK * 32)
#define PINNED_WARPS 9
#define ROW_U4 1536          // uint4 per interleaved row block (3*4096 halves)

#define SMEM_H_BYTES (HDIM * 2)                                  // 8192 (fp16 h)
#define PIN_HALVES (PINNED_WARPS * 3 * HDIM)                     // 110592 halves
#define SMEM_TOTAL (SMEM_H_BYTES + PIN_HALVES * 2)               // 229376 B

__device__ __half g_whh_h[(size_t)3 * HDIM * HDIM];   // 100.7 MB fp16 W_hh (interleaved)
__device__ __half g_wout_h[(size_t)OROWS * HDIM];     // 3.3 MB fp16 W_out
__device__ __half g_h16[2][HDIM];                     // fp16 hidden (dot inputs)
__device__ float  g_gx[3 * HDIM];                     // W_ih @ relu(x) + b_ih
__device__ unsigned g_cnt;
__device__ unsigned g_gen;

__device__ __forceinline__ float warp_sum(float v) {
#pragma unroll
    for (int o = 16; o; o >>= 1) v += __shfl_xor_sync(0xffffffffu, v, o);
    return v;
}

// Sense-reversing grid barrier; all blocks co-resident (grid == #SMs, 1 blk/SM).
__device__ __forceinline__ void grid_sync() {
    __syncthreads();
    if (threadIdx.x == 0) {
        __threadfence();
        unsigned gen = *(volatile unsigned*)&g_gen;
        unsigned nblk = gridDim.x;
        if (atomicAdd(&g_cnt, 1u) == nblk - 1u) {
            atomicExch(&g_cnt, 0u);
            __threadfence();
            atomicAdd(&g_gen, 1u);
        } else {
            while (*(volatile unsigned*)&g_gen == gen) { __nanosleep(32); }
        }
        __threadfence();
    }
    __syncthreads();
}

__device__ __forceinline__ float fast_sigmoid(float x) {
    float e;
    asm("ex2.approx.f32 %0, %1;" : "=f"(e) : "f"(-1.4426950408889634f * x));
    float r;
    asm("rcp.approx.f32 %0, %1;" : "=f"(r) : "f"(1.0f + e));
    return r;
}
__device__ __forceinline__ float fast_tanh(float x) {
    float r;
    asm("tanh.approx.f32 %0, %1;" : "=f"(r) : "f"(x));
    return r;
}

// pack 8 consecutive fp32 -> uint4 of 8 fp16
__device__ __forceinline__ uint4 pack8(const float* src) {
    float4 a = ((const float4*)src)[0];
    float4 b = ((const float4*)src)[1];
    uint4 o;
    *(__half2*)&o.x = __floats2half2_rn(a.x, a.y);
    *(__half2*)&o.y = __floats2half2_rn(a.z, a.w);
    *(__half2*)&o.z = __floats2half2_rn(b.x, b.y);
    *(__half2*)&o.w = __floats2half2_rn(b.z, b.w);
    return o;
}

__global__ void __launch_bounds__(NTHREADS, 1)
decoder_persistent_kernel(const float* __restrict__ start,
                          const float* __restrict__ enc,
                          const float* __restrict__ W_ih,
                          const float* __restrict__ W_hh,
                          const float* __restrict__ b_ih,
                          const float* __restrict__ b_hh,
                          const float* __restrict__ W_out,
                          const float* __restrict__ b_out,
                          const int*   __restrict__ maxlen_ptr,
                          float* __restrict__ out)
{
    extern __shared__ char smem_dyn[];
    __half* h_sh  = (__half*)smem_dyn;                      // 8 KB fp16 h
    __half* pin_w = (__half*)(smem_dyn + SMEM_H_BYTES);     // 216 KB pinned W

    const int lane   = threadIdx.x & 31;
    const int warp   = threadIdx.x >> 5;
    const int gwarp  = blockIdx.x * WARPS_PER_BLOCK + warp;
    const int gwarps = gridDim.x * WARPS_PER_BLOCK;
    const int gtid    = blockIdx.x * NTHREADS + threadIdx.x;
    const int gthreads = gridDim.x * NTHREADS;
    const int T = maxlen_ptr ? *maxlen_ptr : 2048;

    // ---- convert W_hh into INTERLEAVED fp16 scratch ----
    {
        const int total4 = HDIM * ROW_U4;                 // 6,291,456
        uint4* dst = (uint4*)g_whh_h;
        for (int d = gtid; d < total4; d += gthreads) {
            int row = d / ROW_U4;
            int rem = d - row * ROW_U4;
            int it  = rem / 96;
            int r2  = rem - it * 96;
            int s   = r2 >> 5;
            int ln  = r2 & 31;
            int col = (it * 32 + ln) * 8;
            dst[d] = pack8(W_hh + ((size_t)(s * HDIM + row)) * HDIM + col);
        }
        const size_t ototal = (size_t)OROWS * HDIM;
        for (size_t idx = (size_t)gtid * 8; idx < ototal; idx += (size_t)gthreads * 8)
            ((uint4*)(g_wout_h + idx))[0] = pack8(W_out + idx);
    }

    // ---- fill pinned smem weights (same interleaved layout) ----
    {
        uint4* pdst = (uint4*)pin_w;
        for (int idx = threadIdx.x; idx < PINNED_WARPS * ROW_U4; idx += NTHREADS) {
            int w   = idx / ROW_U4;
            int rem = idx - w * ROW_U4;
            int it  = rem / 96;
            int r2  = rem - it * 96;
            int s   = r2 >> 5;
            int ln  = r2 & 31;
            int row = blockIdx.x * WARPS_PER_BLOCK + w;
            if (row < HDIM) {
                int col = (it * 32 + ln) * 8;
                pdst[idx] = pack8(W_hh + ((size_t)(s * HDIM + row)) * HDIM + col);
            }
        }
    }

    // ---- init: h0 (fp16 global for dot inputs) ----
    for (int idx = gtid; idx < HDIM; idx += gthreads)
        g_h16[0][idx] = __float2half_rn(enc[idx]);

    // ---- gx = W_ih @ relu(start) + b_ih (once per launch, fp32) ----
    for (int r = gwarp; r < 3 * HDIM; r += gwarps) {
        const float* wr = W_ih + (size_t)r * IN_DIM;
        float acc = 0.f;
        for (int k = lane; k < IN_DIM; k += 32) {
            float x = start[k];
            x = x > 0.f ? x : 0.f;
            acc += wr[k] * x;
        }
        acc = warp_sum(acc);
        if (lane == 0) g_gx[r] = acc + b_ih[r];
    }
    grid_sync();

    // Stage-B rows assigned to PINNED warps only (no LDG in their Stage A).
    int brow = -1;
    if (warp < PINNED_WARPS) {
        int pid = blockIdx.x * PINNED_WARPS + warp;
        if ((pid % 3) == 0 && (pid / 3) < OROWS) brow = pid / 3;
    }

    const int myrow = (gwarp < HDIM) ? gwarp : -1;

    // hoist per-row constants out of the time loop
    float c_br = 0.f, c_bz = 0.f, c_bn = 0.f, c_gr = 0.f, c_gz = 0.f, c_gn = 0.f;
    if (myrow >= 0) {
        c_br = b_hh[myrow];
        c_bz = b_hh[myrow + HDIM];
        c_bn = b_hh[myrow + 2 * HDIM];
        c_gr = g_gx[myrow];
        c_gz = g_gx[myrow + HDIM];
        c_gn = g_gx[myrow + 2 * HDIM];
    }
    const float c_bo = (brow >= 0) ? b_out[brow] : 0.f;

    const bool pinned = (warp < PINNED_WARPS);

    // one weight base pointer per warp (interleaved layout, fixed all launch)
    const uint4* wbase = pinned
        ? (const uint4*)pin_w + (size_t)warp * ROW_U4
        : (const uint4*)g_whh_h + (size_t)(myrow < 0 ? 0 : myrow) * ROW_U4;

    const __half2 z2 = __float2half2_rn(0.f);

    // register-carried recurrent state: exact fp32 h[i] for this warp's row
    float hreg = (myrow >= 0) ? enc[myrow] : 0.f;

    // ---- main recurrence ----
    for (int t = 0; t < T; t++) {
        const __half* __restrict__ hc16 = g_h16[t & 1];
        __half*       __restrict__ hn16 = g_h16[(t + 1) & 1];
        const uint4* hh = (const uint4*)h_sh;

        // stage fp16 h_cur into shared memory (raw 8 KB copy, no cvt)
        {
            const uint4* src = (const uint4*)hc16;
            uint4* dst = (uint4*)h_sh;
            for (int idx = threadIdx.x; idx < HDIM / 8; idx += NTHREADS)
                dst[idx] = src[idx];
        }
        __syncthreads();

        // Stage A: one warp per output i (flat HFMA2, group-flushed).
        // Interleaved weights: iteration it reads base[it*96 + lane + {0,32,64}].
        if (myrow >= 0) {
            float a0 = 0.f, a1 = 0.f, a2 = 0.f;
#pragma unroll
            for (int g = 0; g < 4; g++) {
                __half2 A0 = z2, B0 = z2, A1 = z2, B1 = z2, A2 = z2, B2 = z2;
#pragma unroll
                for (int j = 0; j < 4; j++) {
                    int it = g * 4 + j;
                    int kb = it * 96 + lane;
                    uint4 u0 = wbase[kb];
                    uint4 u1 = wbase[kb + 32];
                    uint4 u2 = wbase[kb + 64];
                    uint4 hu = hh[it * 32 + lane];
                    __half2 hx = *(const __half2*)&hu.x;
                    __half2 hy = *(const __half2*)&hu.y;
                    __half2 hz = *(const __half2*)&hu.z;
                    __half2 hw = *(const __half2*)&hu.w;
                    A0 = __hfma2(*(const __half2*)&u0.x, hx, A0);
                    B0 = __hfma2(*(const __half2*)&u0.y, hy, B0);
                    A0 = __hfma2(*(const __half2*)&u0.z, hz, A0);
                    B0 = __hfma2(*(const __half2*)&u0.w, hw, B0);
                    A1 = __hfma2(*(const __half2*)&u1.x, hx, A1);
                    B1 = __hfma2(*(const __half2*)&u1.y, hy, B1);
                    A1 = __hfma2(*(const __half2*)&u1.z, hz, A1);
                    B1 = __hfma2(*(const __half2*)&u1.w, hw, B1);
                    A2 = __hfma2(*(const __half2*)&u2.x, hx, A2);
                    B2 = __hfma2(*(const __half2*)&u2.y, hy, B2);
                    A2 = __hfma2(*(const __half2*)&u2.z, hz, A2);
                    B2 = __hfma2(*(const __half2*)&u2.w, hw, B2);
                }
                float2 f0 = __half22float2(__hadd2(A0, B0));
                float2 f1 = __half22float2(__hadd2(A1, B1));
                float2 f2 = __half22float2(__hadd2(A2, B2));
                a0 += f0.x + f0.y;
                a1 += f1.x + f1.y;
                a2 += f2.x + f2.y;
            }
            a0 = warp_sum(a0);
            a1 = warp_sum(a1);
            a2 = warp_sum(a2);
            float r = fast_sigmoid(c_gr + a0 + c_br);
            float z = fast_sigmoid(c_gz + a1 + c_bz);
            float n = fast_tanh(c_gn + r * (a2 + c_bn));
            float hv = (1.f - z) * n + z * hreg;
            hreg = hv;                            // exact fp32 carry in-register
            if (lane == 0)
                hn16[myrow] = __float2half_rn(hv);
        }

        // Stage B (deferred, for step t-1): pinned warps only; h from h_sh.
        if (t > 0 && brow >= 0) {
            const uint4* wr = (const uint4*)(g_wout_h + (size_t)brow * HDIM);
            float acc = 0.f;
#pragma unroll
            for (int g = 0; g < 4; g++) {
                __half2 A = z2, B = z2;
#pragma unroll
                for (int j = 0; j < 4; j++) {
                    int k = lane + (g * 4 + j) * 32;
                    uint4 u = wr[k];
                    uint4 hu = hh[k];
                    A = __hfma2(*(const __half2*)&u.x, *(const __half2*)&hu.x, A);
                    B = __hfma2(*(const __half2*)&u.y, *(const __half2*)&hu.y, B);
                    A = __hfma2(*(const __half2*)&u.z, *(const __half2*)&hu.z, A);
                    B = __hfma2(*(const __half2*)&u.w, *(const __half2*)&hu.w, B);
                }
                float2 f = __half22float2(__hadd2(A, B));
                acc += f.x + f.y;
            }
            acc = warp_sum(acc);
            if (lane == 0) {
                float o = acc + c_bo;
                int tt = t - 1;
                if (brow < NOUT)
                    out[(size_t)tt * NOUT + brow] = fast_tanh(o);
                else
                    out[(size_t)T * NOUT + tt] = fast_sigmoid(o);
            }
        }

        grid_sync();   // h_new(t) globally visible
    }

    // ---- final Stage B for step T-1: fp16 h(T) from global (same math as
    //      every other step's Stage B; h_sh holds h(T-1), so read global) ----
    if (brow >= 0) {
        const uint4* hf = (const uint4*)g_h16[T & 1];
        const uint4* wr = (const uint4*)(g_wout_h + (size_t)brow * HDIM);
        float acc = 0.f;
#pragma unroll
        for (int g = 0; g < 4; g++) {
            __half2 A = z2, B = z2;
#pragma unroll
            for (int j = 0; j < 4; j++) {
                int k = lane + (g * 4 + j) * 32;
                uint4 u = wr[k];
                uint4 hu = hf[k];
                A = __hfma2(*(const __half2*)&u.x, *(const __half2*)&hu.x, A);
                B = __hfma2(*(const __half2*)&u.y, *(const __half2*)&hu.y, B);
                A = __hfma2(*(const __half2*)&u.z, *(const __half2*)&hu.z, A);
                B = __hfma2(*(const __half2*)&u.w, *(const __half2*)&hu.w, B);
            }
            float2 f = __half22float2(__hadd2(A, B));
            acc += f.x + f.y;
        }
        acc = warp_sum(acc);
        if (lane == 0) {
            float o = acc + c_bo;
            int tt = T - 1;
            if (brow < NOUT)
                out[(size_t)tt * NOUT + brow] = fast_tanh(o);
            else
                out[(size_t)T * NOUT + tt] = fast_sigmoid(o);
        }
    }
}

extern "C" void kernel_launch(void* const* d_in, const int* in_sizes, int n_in,
                              void* d_out, int out_size) {
    (void)in_sizes; (void)out_size;

    int dev = 0;
    cudaGetDevice(&dev);
    int sm = 148;
    cudaDeviceGetAttribute(&sm, cudaDevAttrMultiProcessorCount, dev);
    if (sm < 1) sm = 148;
    if (sm > 512) sm = 512;

    cudaFuncSetAttribute(decoder_persistent_kernel,
                         cudaFuncAttributeMaxDynamicSharedMemorySize, SMEM_TOTAL);

    const float* start = (const float*)d_in[0];
    const float* enc   = (const float*)d_in[1];
    const float* W_ih  = (const float*)d_in[2];
    const float* W_hh  = (const float*)d_in[3];
    const float* b_ih  = (const float*)d_in[4];
    const float* b_hh  = (const float*)d_in[5];
    const float* W_out = (const float*)d_in[6];
    const float* b_out = (const float*)d_in[7];
    const int* maxlen  = (n_in > 8) ? (const int*)d_in[8] : nullptr;

    decoder_persistent_kernel<<<sm, NTHREADS, SMEM_TOTAL>>>(
        start, enc, W_ih, W_hh, b_ih, b_hh, W_out, b_out, maxlen, (float*)d_out);
}